// round 10
// baseline (speedup 1.0000x reference)
#include <cuda_runtime.h>

// MSELoss: out = mean((yhat - y)^2) over 16384 x 4096 fp32.
// Best-measured body (R9) + final grid tune:
//  - 256-bit streaming loads with L1/L2 evict_first (measured +1% DRAM vs
//    plain v8 on identical body; sm_103a requires .v8.f32 for the L2 hint)
//  - grid=2960 (148 x 20, 2.5 residency waves): finer rebalance granularity
//    over the CTA-spread tail than 2368, fewer transitions than 4736
//  - __launch_bounds__(256,8): regs pinned <= 32, full residency
//  - fused finalize: device scratch + last-block-done, single graph node

#define BLOCK 256
#define GRID  2960   // 148 * 20

__device__ float    g_sum   = 0.0f;
__device__ unsigned g_count = 0u;

__device__ __forceinline__ void ldg256_stream(const float* p,
                                              float& v0, float& v1, float& v2, float& v3,
                                              float& v4, float& v5, float& v6, float& v7) {
    asm volatile("ld.global.nc.L1::evict_first.L2::evict_first.v8.f32 "
                 "{%0,%1,%2,%3,%4,%5,%6,%7}, [%8];"
                 : "=f"(v0), "=f"(v1), "=f"(v2), "=f"(v3),
                   "=f"(v4), "=f"(v5), "=f"(v6), "=f"(v7)
                 : "l"(p));
}

__global__ void __launch_bounds__(BLOCK, 8)
mse_kernel(const float* __restrict__ yhat,
           const float* __restrict__ y,
           float* __restrict__ out,
           int n8, float inv_n) {
    float acc = 0.0f;
    const int stride = GRID * BLOCK;
    for (int i = blockIdx.x * BLOCK + threadIdx.x; i < n8; i += stride) {
        const float* pa = yhat + (size_t)i * 8;
        const float* pb = y    + (size_t)i * 8;
        float a0, a1, a2, a3, a4, a5, a6, a7;
        float b0, b1, b2, b3, b4, b5, b6, b7;
        ldg256_stream(pa, a0, a1, a2, a3, a4, a5, a6, a7);
        ldg256_stream(pb, b0, b1, b2, b3, b4, b5, b6, b7);
        float d;
        d = a0 - b0; acc = fmaf(d, d, acc);
        d = a1 - b1; acc = fmaf(d, d, acc);
        d = a2 - b2; acc = fmaf(d, d, acc);
        d = a3 - b3; acc = fmaf(d, d, acc);
        d = a4 - b4; acc = fmaf(d, d, acc);
        d = a5 - b5; acc = fmaf(d, d, acc);
        d = a6 - b6; acc = fmaf(d, d, acc);
        d = a7 - b7; acc = fmaf(d, d, acc);
    }

    // warp reduce
    #pragma unroll
    for (int off = 16; off > 0; off >>= 1)
        acc += __shfl_xor_sync(0xFFFFFFFFu, acc, off);

    __shared__ float warp_sums[BLOCK / 32];
    int lane = threadIdx.x & 31;
    int wid  = threadIdx.x >> 5;
    if (lane == 0) warp_sums[wid] = acc;
    __syncthreads();

    if (threadIdx.x == 0) {
        float bsum = 0.0f;
        #pragma unroll
        for (int w = 0; w < BLOCK / 32; w++) bsum += warp_sums[w];

        float prior = atomicAdd(&g_sum, bsum);
        __threadfence();
        unsigned t = atomicAdd(&g_count, 1u);
        if (t == GRID - 1) {
            out[0] = (prior + bsum) * inv_n;
            g_sum   = 0.0f;   // reset for next graph replay
            g_count = 0u;
        }
    }
}

extern "C" void kernel_launch(void* const* d_in, const int* in_sizes, int n_in,
                              void* d_out, int out_size) {
    const float* yhat = (const float*)d_in[0];
    const float* y    = (const float*)d_in[1];
    float* out = (float*)d_out;

    long long n = (long long)in_sizes[0];   // 67108864
    int n8 = (int)(n / 8);                  // 8388608 (16384*4096 % 8 == 0)
    float inv_n = 1.0f / (float)n;

    mse_kernel<<<GRID, BLOCK>>>(yhat, y, out, n8, inv_n);
}

// round 11
// speedup vs baseline: 1.0033x; 1.0033x over previous
#include <cuda_runtime.h>

// MSELoss: out = mean((yhat - y)^2) over 16384 x 4096 fp32.  FINAL (R9 config).
// Session-converged best configuration:
//  - 256-bit streaming loads with L1::evict_first.L2::evict_first
//    (sm_103a requires .v8.f32 width for the L2 hint; policy measured
//    +1% DRAM over plain v8 on the identical body)
//  - grid=2368 = 148 SMs x 16 blocks = exactly 2 residency waves
//    (swept 1/2/2.5/4 waves: 2 integer waves measured best)
//  - __launch_bounds__(256,8): regs pinned at 32, full 8-block residency
//  - fused finalize: device scratch + last-block-done -> single graph node
// Measured: kernel 77.7us, 6960 GB/s (87% of HBM spec), DRAM-bound roofline.

#define BLOCK 256
#define GRID  2368   // 148 * 16

__device__ float    g_sum   = 0.0f;
__device__ unsigned g_count = 0u;

__device__ __forceinline__ void ldg256_stream(const float* p,
                                              float& v0, float& v1, float& v2, float& v3,
                                              float& v4, float& v5, float& v6, float& v7) {
    asm volatile("ld.global.nc.L1::evict_first.L2::evict_first.v8.f32 "
                 "{%0,%1,%2,%3,%4,%5,%6,%7}, [%8];"
                 : "=f"(v0), "=f"(v1), "=f"(v2), "=f"(v3),
                   "=f"(v4), "=f"(v5), "=f"(v6), "=f"(v7)
                 : "l"(p));
}

__global__ void __launch_bounds__(BLOCK, 8)
mse_kernel(const float* __restrict__ yhat,
           const float* __restrict__ y,
           float* __restrict__ out,
           int n8, float inv_n) {
    float acc = 0.0f;
    const int stride = GRID * BLOCK;
    for (int i = blockIdx.x * BLOCK + threadIdx.x; i < n8; i += stride) {
        const float* pa = yhat + (size_t)i * 8;
        const float* pb = y    + (size_t)i * 8;
        float a0, a1, a2, a3, a4, a5, a6, a7;
        float b0, b1, b2, b3, b4, b5, b6, b7;
        ldg256_stream(pa, a0, a1, a2, a3, a4, a5, a6, a7);
        ldg256_stream(pb, b0, b1, b2, b3, b4, b5, b6, b7);
        float d;
        d = a0 - b0; acc = fmaf(d, d, acc);
        d = a1 - b1; acc = fmaf(d, d, acc);
        d = a2 - b2; acc = fmaf(d, d, acc);
        d = a3 - b3; acc = fmaf(d, d, acc);
        d = a4 - b4; acc = fmaf(d, d, acc);
        d = a5 - b5; acc = fmaf(d, d, acc);
        d = a6 - b6; acc = fmaf(d, d, acc);
        d = a7 - b7; acc = fmaf(d, d, acc);
    }

    // warp reduce
    #pragma unroll
    for (int off = 16; off > 0; off >>= 1)
        acc += __shfl_xor_sync(0xFFFFFFFFu, acc, off);

    __shared__ float warp_sums[BLOCK / 32];
    int lane = threadIdx.x & 31;
    int wid  = threadIdx.x >> 5;
    if (lane == 0) warp_sums[wid] = acc;
    __syncthreads();

    if (threadIdx.x == 0) {
        float bsum = 0.0f;
        #pragma unroll
        for (int w = 0; w < BLOCK / 32; w++) bsum += warp_sums[w];

        float prior = atomicAdd(&g_sum, bsum);
        __threadfence();
        unsigned t = atomicAdd(&g_count, 1u);
        if (t == GRID - 1) {
            out[0] = (prior + bsum) * inv_n;
            g_sum   = 0.0f;   // reset for next graph replay
            g_count = 0u;
        }
    }
}

extern "C" void kernel_launch(void* const* d_in, const int* in_sizes, int n_in,
                              void* d_out, int out_size) {
    const float* yhat = (const float*)d_in[0];
    const float* y    = (const float*)d_in[1];
    float* out = (float*)d_out;

    long long n = (long long)in_sizes[0];   // 67108864
    int n8 = (int)(n / 8);                  // 8388608 (16384*4096 % 8 == 0)
    float inv_n = 1.0f / (float)n;

    mse_kernel<<<GRID, BLOCK>>>(yhat, y, out, n8, inv_n);
}

// round 12
// speedup vs baseline: 1.0037x; 1.0004x over previous
#include <cuda_runtime.h>

// MSELoss: out = mean((yhat - y)^2) over 16384 x 4096 fp32.  FINAL.
// Session-converged configuration (all levers measured):
//  - 256-bit streaming loads, L1::evict_first.L2::evict_first
//  - grid=2368 = 148 SMs x 16 = exactly 2 full-occupancy residency waves
//  - __launch_bounds__(256,8): regs <= 32, 8 blocks/SM resident
//  - pointer-increment loop (no per-iter IMAD address chain)
//  - fused finalize: device scratch + last-block-done, single graph node
// Measured envelope: kernel ~77.7-79us, 6.85-6.96 TB/s (86-88% of HBM spec).

#define BLOCK 256
#define GRID  2368   // 148 * 16

__device__ float    g_sum   = 0.0f;
__device__ unsigned g_count = 0u;

__device__ __forceinline__ void ldg256_stream(const float* p,
                                              float& v0, float& v1, float& v2, float& v3,
                                              float& v4, float& v5, float& v6, float& v7) {
    asm volatile("ld.global.nc.L1::evict_first.L2::evict_first.v8.f32 "
                 "{%0,%1,%2,%3,%4,%5,%6,%7}, [%8];"
                 : "=f"(v0), "=f"(v1), "=f"(v2), "=f"(v3),
                   "=f"(v4), "=f"(v5), "=f"(v6), "=f"(v7)
                 : "l"(p));
}

__global__ void __launch_bounds__(BLOCK, 8)
mse_kernel(const float* __restrict__ yhat,
           const float* __restrict__ y,
           float* __restrict__ out,
           int n8, float inv_n) {
    float acc = 0.0f;
    const int tid0   = blockIdx.x * BLOCK + threadIdx.x;
    const int stride = GRID * BLOCK;               // in v8 units
    const size_t step = (size_t)stride * 8;        // floats per stride

    const float* pa = yhat + (size_t)tid0 * 8;
    const float* pb = y    + (size_t)tid0 * 8;

    for (int i = tid0; i < n8; i += stride, pa += step, pb += step) {
        float a0, a1, a2, a3, a4, a5, a6, a7;
        float b0, b1, b2, b3, b4, b5, b6, b7;
        ldg256_stream(pa, a0, a1, a2, a3, a4, a5, a6, a7);
        ldg256_stream(pb, b0, b1, b2, b3, b4, b5, b6, b7);
        float d;
        d = a0 - b0; acc = fmaf(d, d, acc);
        d = a1 - b1; acc = fmaf(d, d, acc);
        d = a2 - b2; acc = fmaf(d, d, acc);
        d = a3 - b3; acc = fmaf(d, d, acc);
        d = a4 - b4; acc = fmaf(d, d, acc);
        d = a5 - b5; acc = fmaf(d, d, acc);
        d = a6 - b6; acc = fmaf(d, d, acc);
        d = a7 - b7; acc = fmaf(d, d, acc);
    }

    // warp reduce
    #pragma unroll
    for (int off = 16; off > 0; off >>= 1)
        acc += __shfl_xor_sync(0xFFFFFFFFu, acc, off);

    __shared__ float warp_sums[BLOCK / 32];
    int lane = threadIdx.x & 31;
    int wid  = threadIdx.x >> 5;
    if (lane == 0) warp_sums[wid] = acc;
    __syncthreads();

    if (threadIdx.x == 0) {
        float bsum = 0.0f;
        #pragma unroll
        for (int w = 0; w < BLOCK / 32; w++) bsum += warp_sums[w];

        float prior = atomicAdd(&g_sum, bsum);
        __threadfence();
        unsigned t = atomicAdd(&g_count, 1u);
        if (t == GRID - 1) {
            out[0] = (prior + bsum) * inv_n;
            g_sum   = 0.0f;   // reset for next graph replay
            g_count = 0u;
        }
    }
}

extern "C" void kernel_launch(void* const* d_in, const int* in_sizes, int n_in,
                              void* d_out, int out_size) {
    const float* yhat = (const float*)d_in[0];
    const float* y    = (const float*)d_in[1];
    float* out = (float*)d_out;

    long long n = (long long)in_sizes[0];   // 67108864
    int n8 = (int)(n / 8);                  // 8388608 (16384*4096 % 8 == 0)
    float inv_n = 1.0f / (float)n;

    mse_kernel<<<GRID, BLOCK>>>(yhat, y, out, n8, inv_n);
}